// round 5
// baseline (speedup 1.0000x reference)
#include <cuda_runtime.h>

// Problem constants: B=8, N=1024, C=768, H=12, D=64.
//
// Mathematical collapse: the reference replaces V with spe_agg broadcast over
// the sequence axis, so V is independent of the attention key index m.
// Hence  Σ_m softmax(q·k)[n,m] * v[m] = v * Σ_m softmax = v  (softmax rows sum
// to 1 exactly). The attention block is the identity on this V, and:
//   out[b, n, j] = Σ_c spe_agg[b,c] * W_proj[j,c] + b_proj[j]   (constant in n)
// x and W_qkv are mathematically unused.

#define Bk 8
#define Ck 768
#define Nk 1024
#define C4 (Ck / 4)          // 192 float4 per row

// Scratch for y = spe_agg @ W_proj^T + b_proj  (8 x 768 floats = 24 KB).
// __device__ global: allocation-free per harness rules. Referenced directly
// from device code in both kernels — no host-side symbol lookup needed.
__device__ float4 g_y[Bk * C4];

// ---------------------------------------------------------------------------
// Kernel A: tiny GEMM. One warp computes one output element y[b][j].
// grid = (B, C/8) = (8, 96), block = 256 threads (8 warps).
// Fully coalesced float4 reads of the W_proj row and the spe_agg row.
// ---------------------------------------------------------------------------
__global__ void __launch_bounds__(256) proj_kernel(
    const float* __restrict__ spe_agg,   // (B, C)
    const float* __restrict__ W_proj,    // (C, C) row-major, y = s @ W^T
    const float* __restrict__ b_proj)    // (C,)
{
    const int b    = blockIdx.x;
    const int warp = threadIdx.x >> 5;
    const int lane = threadIdx.x & 31;
    const int j    = blockIdx.y * 8 + warp;

    const float4* __restrict__ Wrow =
        reinterpret_cast<const float4*>(W_proj + (size_t)j * Ck);
    const float4* __restrict__ srow =
        reinterpret_cast<const float4*>(spe_agg + (size_t)b * Ck);

    float acc = 0.0f;
    #pragma unroll
    for (int i = 0; i < C4 / 32; ++i) {          // 6 iterations: 6*32*4 = 768
        float4 w = Wrow[i * 32 + lane];
        float4 s = srow[i * 32 + lane];
        acc += w.x * s.x + w.y * s.y + w.z * s.z + w.w * s.w;
    }
    #pragma unroll
    for (int off = 16; off > 0; off >>= 1)
        acc += __shfl_xor_sync(0xffffffffu, acc, off);

    if (lane == 0) {
        float* yf = reinterpret_cast<float*>(g_y);
        yf[b * Ck + j] = acc + __ldg(&b_proj[j]);
    }
}

// ---------------------------------------------------------------------------
// Kernel B: broadcast y over the sequence axis. Pure streaming STG.128.
// One float4 per thread. Total = B*N*C/4 = 1,572,864 float4 = 25.2 MB.
// g_y (24 KB) stays L1/L2-hot; this kernel should sit at the DRAM-write
// ceiling.
// ---------------------------------------------------------------------------
__global__ void __launch_bounds__(256) bcast_kernel(float4* __restrict__ out)
{
    const int idx = blockIdx.x * blockDim.x + threadIdx.x;   // 0 .. 1572863
    const int b   = idx / (Nk * C4);                         // /196608 (const div)
    const int j4  = idx % C4;                                // %192    (const mod)
    out[idx] = g_y[b * C4 + j4];
}

extern "C" void kernel_launch(void* const* d_in, const int* in_sizes, int n_in,
                              void* d_out, int out_size)
{
    // metadata order: x, spe_agg, W_qkv, W_proj, b_proj
    const float* spe_agg = (const float*)d_in[1];
    const float* W_proj  = (const float*)d_in[3];
    const float* b_proj  = (const float*)d_in[4];
    float4* out          = (float4*)d_out;

    (void)in_sizes; (void)n_in; (void)out_size;

    dim3 gridA(Bk, Ck / 8);                   // (8, 96) blocks, 1 warp per j
    proj_kernel<<<gridA, 256>>>(spe_agg, W_proj, b_proj);

    const int total4 = Bk * Nk * C4;          // 1,572,864
    bcast_kernel<<<total4 / 256, 256>>>(out); // 6144 blocks — full-chip stores
}

// round 7
// speedup vs baseline: 1.0426x; 1.0426x over previous
#include <cuda_runtime.h>
#include <cstdint>

// Problem constants: B=8, N=1024, C=768, H=12, D=64.
//
// Mathematical collapse: V = spe_agg broadcast over the sequence axis is
// independent of the attention key index m, so Σ_m softmax(...)·v = v
// (softmax rows sum to 1). The whole module reduces to
//   out[b, n, j] = Σ_c spe_agg[b,c] * W_proj[j,c] + b_proj[j]  (constant in n)
// x and W_qkv are mathematically unused.

#define Bk 8
#define Ck 768
#define Nk 1024
#define C4 (Ck / 4)          // 192 float4 per y-row
#define REP 8                // y-row replicas staged in smem (8*3KB = 24KB)
#define NPB 64               // n-rows written per block
#define NCHUNK (Nk / NPB)    // 16 n-chunks per batch row

// y = spe_agg @ W_proj^T + b_proj  (8 x 768 floats = 24 KB), device scratch.
__device__ float4 g_y[Bk * C4];

__device__ __forceinline__ uint32_t smem_u32(const void* p) {
    uint32_t a;
    asm("{ .reg .u64 t; cvta.to.shared.u64 t, %1; cvt.u32.u64 %0, t; }"
        : "=r"(a) : "l"(p));
    return a;
}

// ---------------------------------------------------------------------------
// Kernel A: tiny GEMM. One warp per output element y[b][j].
// grid = (B, C/8) = (8, 96), block = 256. Coalesced float4 reads; W_proj
// (2.36 MB) stays L2-resident across graph replays.
// ---------------------------------------------------------------------------
__global__ void __launch_bounds__(256) proj_kernel(
    const float* __restrict__ spe_agg,   // (B, C)
    const float* __restrict__ W_proj,    // (C, C) row-major
    const float* __restrict__ b_proj)    // (C,)
{
    const int b    = blockIdx.x;
    const int warp = threadIdx.x >> 5;
    const int lane = threadIdx.x & 31;
    const int j    = blockIdx.y * 8 + warp;

    const float4* __restrict__ Wrow =
        reinterpret_cast<const float4*>(W_proj + (size_t)j * Ck);
    const float4* __restrict__ srow =
        reinterpret_cast<const float4*>(spe_agg + (size_t)b * Ck);

    float acc = 0.0f;
    #pragma unroll
    for (int i = 0; i < C4 / 32; ++i) {          // 6 iters, MLP=12 loads
        float4 w = Wrow[i * 32 + lane];
        float4 s = srow[i * 32 + lane];
        acc += w.x * s.x + w.y * s.y + w.z * s.z + w.w * s.w;
    }
    #pragma unroll
    for (int off = 16; off > 0; off >>= 1)
        acc += __shfl_xor_sync(0xffffffffu, acc, off);

    if (lane == 0) {
        float* yf = reinterpret_cast<float*>(g_y);
        yf[b * Ck + j] = acc + __ldg(&b_proj[j]);
    }
}

// ---------------------------------------------------------------------------
// Kernel B: broadcast y[b] over the sequence axis via TMA bulk stores.
// grid = (NCHUNK, B) = (16, 8) = 128 blocks. Each block:
//   1. stages y[b] replicated REP times in smem (24 KB)
//   2. issues NPB/REP = 8 cp.async.bulk stores of 24 KB each
// Store issue cost: 8 instructions per 192 KB instead of 12288 STG.128 —
// removes the SM issue bottleneck seen in R5 (issue=15.8%, DRAM=0%).
// ---------------------------------------------------------------------------
__global__ void __launch_bounds__(256) bcast_kernel(float* __restrict__ out)
{
    __shared__ __align__(16) float4 s[REP * C4];   // 24 KB

    const int b     = blockIdx.y;
    const int chunk = blockIdx.x;

    // Replicate y[b] (192 float4) REP times: 1536 float4, 6 per thread.
    const float4* __restrict__ yrow = g_y + b * C4;
    #pragma unroll
    for (int i = threadIdx.x; i < REP * C4; i += 256)
        s[i] = yrow[i % C4];

    __syncthreads();
    asm volatile("fence.proxy.async.shared::cta;" ::: "memory");  // generic->async proxy

    if (threadIdx.x == 0) {
        const uint32_t saddr = smem_u32(s);
        float* base = out + ((size_t)b * Nk + (size_t)chunk * NPB) * Ck;
        #pragma unroll
        for (int i = 0; i < NPB / REP; ++i) {                     // 8 copies
            asm volatile(
                "cp.async.bulk.global.shared::cta.bulk_group [%0], [%1], %2;"
                :: "l"(base + (size_t)i * REP * Ck), "r"(saddr),
                   "n"(REP * Ck * 4)
                : "memory");
        }
        asm volatile("cp.async.bulk.commit_group;" ::: "memory");
        asm volatile("cp.async.bulk.wait_group 0;" ::: "memory");
    }
}

extern "C" void kernel_launch(void* const* d_in, const int* in_sizes, int n_in,
                              void* d_out, int out_size)
{
    // metadata order: x, spe_agg, W_qkv, W_proj, b_proj
    const float* spe_agg = (const float*)d_in[1];
    const float* W_proj  = (const float*)d_in[3];
    const float* b_proj  = (const float*)d_in[4];
    float* out           = (float*)d_out;

    (void)in_sizes; (void)n_in; (void)out_size;

    dim3 gridA(Bk, Ck / 8);                   // (8, 96)
    proj_kernel<<<gridA, 256>>>(spe_agg, W_proj, b_proj);

    dim3 gridB(NCHUNK, Bk);                   // (16, 8)
    bcast_kernel<<<gridB, 256>>>(out);
}

// round 11
// speedup vs baseline: 1.2381x; 1.1875x over previous
#include <cuda_runtime.h>
#include <cstdint>

// B=8, N=1024, C=768, H=12, D=64.
//
// Mathematical collapse: V = spe_agg broadcast over the sequence axis is
// independent of the attention key index m, so Σ_m softmax(...)·v = v
// (softmax rows sum to exactly 1). The whole module reduces to
//   out[b, n, j] = Σ_c spe_agg[b,c] * W_proj[j,c] + b_proj[j]   (constant in n)
// x and W_qkv are mathematically unused.
//
// R7 finding: the 25.2 MB output write stream floors at ~8.1 µs regardless of
// store mechanism (STG vs TMA bulk) -> HW write-drain bound. So: single fused
// kernel; the tiny GEMV rides under the store stream, removing the separate
// proj kernel + inter-kernel gap (~4.6 us in R7).

#define Bk 8
#define Ck 768
#define Nk 1024
#define JS 48                 // j-columns per block (48 floats = 12 float4)
#define JS4 (JS / 4)          // 12
#define NJ (Ck / JS)          // 16 j-slices
#define TPB 384               // 12 warps: 4 j's per warp; 12 f4-cols * 32 rows/pass

__global__ void __launch_bounds__(TPB) fused_kernel(
    const float* __restrict__ spe_agg,   // (B, C)
    const float* __restrict__ W_proj,    // (C, C) row-major
    const float* __restrict__ b_proj,    // (C,)
    float* __restrict__ out)             // (B, N, C)
{
    __shared__ __align__(16) float y_s[JS];

    const int b     = blockIdx.y;        // 0..7
    const int jbase = blockIdx.x * JS;   // 0,48,...,720
    const int tid   = threadIdx.x;
    const int warp  = tid >> 5;          // 0..11
    const int lane  = tid & 31;

    // ---- Phase 1: compute y[b][jbase .. jbase+47] -------------------------
    // Each warp computes 4 j's. spe_agg row cached in registers (6 float4).
    const float4* __restrict__ srow =
        reinterpret_cast<const float4*>(spe_agg + (size_t)b * Ck);
    float4 sreg[6];
    #pragma unroll
    for (int i = 0; i < 6; ++i) sreg[i] = srow[i * 32 + lane];

    #pragma unroll
    for (int jj = 0; jj < 4; ++jj) {
        const int j = jbase + warp * 4 + jj;
        const float4* __restrict__ Wrow =
            reinterpret_cast<const float4*>(W_proj + (size_t)j * Ck);
        float acc = 0.0f;
        #pragma unroll
        for (int i = 0; i < 6; ++i) {
            float4 w = Wrow[i * 32 + lane];
            acc += w.x * sreg[i].x + w.y * sreg[i].y
                 + w.z * sreg[i].z + w.w * sreg[i].w;
        }
        #pragma unroll
        for (int off = 16; off > 0; off >>= 1)
            acc += __shfl_xor_sync(0xffffffffu, acc, off);
        if (lane == 0)
            y_s[warp * 4 + jj] = acc + __ldg(&b_proj[j]);
    }
    __syncthreads();

    // ---- Phase 2: broadcast the 48-float slice over all 1024 n-rows -------
    // thread -> (f4-column, starting row); value pinned in a register, then
    // 32 pure STG.128s with stride 1024 rows/32. Fully coalesced: threads
    // 0..11 cover one row's 192B segment.
    const int f  = tid % JS4;            // 0..11
    const int r0 = tid / JS4;            // 0..31
    const float4 val = reinterpret_cast<const float4*>(y_s)[f];

    float* obase = out + (size_t)b * Nk * Ck + jbase;
    #pragma unroll
    for (int it = 0; it < Nk / (TPB / JS4); ++it) {      // 32 iterations
        const int r = r0 + it * (TPB / JS4);
        reinterpret_cast<float4*>(obase + (size_t)r * Ck)[f] = val;
    }
}

extern "C" void kernel_launch(void* const* d_in, const int* in_sizes, int n_in,
                              void* d_out, int out_size)
{
    // metadata order: x, spe_agg, W_qkv, W_proj, b_proj
    const float* spe_agg = (const float*)d_in[1];
    const float* W_proj  = (const float*)d_in[3];
    const float* b_proj  = (const float*)d_in[4];
    float* out           = (float*)d_out;

    (void)in_sizes; (void)n_in; (void)out_size;

    dim3 grid(NJ, Bk);                    // (16, 8) = 128 blocks
    fused_kernel<<<grid, TPB>>>(spe_agg, W_proj, b_proj, out);
}